// round 16
// baseline (speedup 1.0000x reference)
#include <cuda_runtime.h>
#include <math.h>
#include <stdint.h>

#define B_  2
#define T_  4096
#define C_  1024
#define H_  16
#define HD_ 64
#define W_  256
#define NW_ (T_/W_)
#define M_  (B_*T_)

// Scratch (no cudaMalloc allowed)
__device__ float g_q[(size_t)M_*C_];
__device__ float g_k[(size_t)M_*C_];
__device__ float g_v[(size_t)M_*C_];
__device__ float g_y[(size_t)M_*C_];

// ===========================================================================
// helpers (baseline ISA only)
// ===========================================================================
__device__ __forceinline__ uint32_t f2tf32(float f) {
    uint32_t r;
    asm("cvt.rna.tf32.f32 %0, %1;" : "=r"(r) : "f"(f));
    return r;
}

__device__ __forceinline__ uint32_t smem_u32(const void* p) {
    uint32_t a;
    asm("{ .reg .u64 t; cvta.to.shared.u64 t, %1; cvt.u32.u64 %0, t; }"
        : "=r"(a) : "l"(p));
    return a;
}

__device__ __forceinline__ void cp_async16(uint32_t dst, const void* src) {
    asm volatile("cp.async.ca.shared.global [%0], [%1], 16;"
                 :: "r"(dst), "l"(src) : "memory");
}
#define CP_COMMIT() asm volatile("cp.async.commit_group;" ::: "memory")
#define CP_WAIT1()  asm volatile("cp.async.wait_group 1;" ::: "memory")

// m16n8k8 tf32 MMA, D += A*B (row.col), fp32 accumulate
__device__ __forceinline__ void mma_tf32(float* d, const uint32_t* a, const uint32_t* b) {
    asm volatile(
        "mma.sync.aligned.m16n8k8.row.col.f32.tf32.tf32.f32 "
        "{%0,%1,%2,%3}, {%4,%5,%6,%7}, {%8,%9}, {%0,%1,%2,%3};"
        : "+f"(d[0]), "+f"(d[1]), "+f"(d[2]), "+f"(d[3])
        : "r"(a[0]), "r"(a[1]), "r"(a[2]), "r"(a[3]),
          "r"(b[0]), "r"(b[1]));
}

// ===========================================================================
// tf32 GEMM (NT) — R15 micro-kernel + A-FRAGMENT DOUBLE-BUFFER across ks.
// Multi-weight fused: slab = blockIdx.x picks (mat, ncol0).
// CTA tile 128x256, 512 threads = 16 warps (2x8), warp tile 64x32
// (4 warps/SMSP). BK=32, cvt.rna at fragment load, cp.async 2-stage ring,
// stage-after-compute with 2 barriers/chunk. A-fragments for ks+1 are loaded
// BEFORE the MMAs of ks (breaks the serial LDS->MMA WAR chain; A is 2/3 of
// fragment traffic). B-fragments single-buffered, loaded after MMAs issue.
// Regs: acc 64 + af 32 + bfr 8 + addressing ~16 <= 128 (no spill).
// rope fused in epilogue.
// ===========================================================================
#define SA 36                          // smem row stride in floats
#define A_F (128 * SA)                 // 4608 floats
#define BT_F (256 * SA)                // 9216 floats
#define STAGE_F (A_F + BT_F)           // 13824
#define GEMM_SMEM_BYTES (2 * STAGE_F * 4)   // 110592 B

__global__ __launch_bounds__(512)
void gemm_fused(const float* __restrict__ A,
                const float* __restrict__ W0, const float* __restrict__ W1,
                const float* __restrict__ W2,
                float* __restrict__ O0, float* __restrict__ O1,
                float* __restrict__ O2, int ropeMask)
{
    extern __shared__ float sm[];
    const uint32_t smb = smem_u32(sm);

    const int tid  = threadIdx.x;
    const int wid  = tid >> 5, lane = tid & 31;
    const int wm   = wid >> 3, wn = wid & 7;     // 2 x 8 warp grid
    const int g    = lane >> 2, tig = lane & 3;  // fragment coords
    const int slab = blockIdx.x;
    const int mat  = slab >> 2;
    const int ncol0 = (slab & 3) * 256;
    const int m0   = blockIdx.y * 128;

    const float* Wt = (mat == 0) ? W0 : ((mat == 1) ? W1 : W2);
    float*       Ot = (mat == 0) ? O0 : ((mat == 1) ? O1 : O2);
    const bool rope = (ropeMask >> mat) & 1;

    // staging mapping (512 threads, BK=32):
    // A tile 128x32: 1024 float4 -> 2 per thread: row=tid>>2, c4=(tid&3)*2
    // B tile 256x32: 2048 float4 -> 4 per thread: row=tid>>1, c4=(tid&1)*4
    const int arow = tid >> 2, ac4 = (tid & 3) * 2;
    const int brow = tid >> 1, bc4 = (tid & 1) * 4;
    const float* AgK = A  + (size_t)(m0 + arow) * C_ + ac4 * 4;
    const float* BgK = Wt + (size_t)(ncol0 + brow) * C_ + bc4 * 4;
    const uint32_t dA0 = smb + (uint32_t)(arow * SA + ac4 * 4) * 4;
    const uint32_t dB0 = smb + (uint32_t)(A_F + brow * SA + bc4 * 4) * 4;

    float acc[16][4];
#pragma unroll
    for (int i = 0; i < 16; i++)
#pragma unroll
        for (int j = 0; j < 4; j++) acc[i][j] = 0.f;

    auto stage = [&](int k0, int s) {
        const uint32_t off = (uint32_t)s * (STAGE_F * 4);
        cp_async16(dA0 + off,      AgK + k0);
        cp_async16(dA0 + off + 16, AgK + k0 + 4);
        cp_async16(dB0 + off,      BgK + k0);
        cp_async16(dB0 + off + 16, BgK + k0 + 4);
        cp_async16(dB0 + off + 32, BgK + k0 + 8);
        cp_async16(dB0 + off + 48, BgK + k0 + 12);
    };

    // ---- prologue: chunks 0,1 -> stages 0,1 ----
    stage(0, 0);  CP_COMMIT();
    stage(32, 1); CP_COMMIT();

    uint32_t af[2][4][4], bfr[4][2];

    for (int c = 0; c < 32; c++) {
        CP_WAIT1();                     // chunk c landed (chunk c+1 may fly)
        __syncthreads();

        const float* sA = sm + (c & 1) * STAGE_F + (wm * 64) * SA;
        const float* sB = sm + (c & 1) * STAGE_F + A_F + (wn * 32) * SA;

        auto lf_a = [&](int ks, uint32_t (&af_)[4][4]) {
            const int kb = ks * 8;
#pragma unroll
            for (int mt = 0; mt < 4; mt++) {
                const float* p = sA + (mt * 16 + g) * SA + kb + tig;
                af_[mt][0] = f2tf32(p[0]);
                af_[mt][1] = f2tf32(p[8 * SA]);
                af_[mt][2] = f2tf32(p[4]);
                af_[mt][3] = f2tf32(p[8 * SA + 4]);
            }
        };
        auto lf_b = [&](int ks) {
            const int kb = ks * 8;
#pragma unroll
            for (int nt = 0; nt < 4; nt++) {
                const float* p = sB + (nt * 8 + g) * SA + kb + tig;
                bfr[nt][0] = f2tf32(p[0]);
                bfr[nt][1] = f2tf32(p[4]);
            }
        };

        lf_a(0, af[0]);
        lf_b(0);
#pragma unroll
        for (int ks = 0; ks < 4; ks++) {
            const int cur = ks & 1;
            // prefetch next A-fragments BEFORE this step's MMAs (hides LDS lat)
            if (ks < 3) lf_a(ks + 1, af[cur ^ 1]);
#pragma unroll
            for (int mt = 0; mt < 4; mt++)
#pragma unroll
                for (int nt = 0; nt < 4; nt++)
                    mma_tf32(acc[mt * 4 + nt], af[cur][mt], bfr[nt]);
            // B regs free after MMA issue; reload for next step
            if (ks < 3) lf_b(ks + 1);
        }

        __syncthreads();                // everyone done reading stage c&1
        if (c + 2 < 32) stage((c + 2) * 32, c & 1);
        CP_COMMIT();                    // keep group count in lockstep
    }

    // -------- epilogue --------
    const int mbase = m0 + wm * 64;
    const int nbase = ncol0 + wn * 32;
#pragma unroll
    for (int nt = 0; nt < 4; nt++) {
        const int nn = nbase + nt * 8 + 2 * tig;
        float invf = 1.f, sv0, cv0, sv1, cv1;
        if (rope) {
            const int ip = (nn & (HD_ - 1)) >> 1;
            invf = (float)exp(-0.28782313662425572 * (double)ip); // ln(1e4)/32
        }
#pragma unroll
        for (int mt = 0; mt < 4; mt++) {
            const float* cc = acc[mt * 4 + nt];
            const int r0 = mbase + mt * 16 + g;
            const int r1 = r0 + 8;
            float2 v01 = make_float2(cc[0], cc[1]);
            float2 v23 = make_float2(cc[2], cc[3]);
            if (rope) {
                sincosf((float)(r0 & (T_ - 1)) * invf, &sv0, &cv0);
                sincosf((float)(r1 & (T_ - 1)) * invf, &sv1, &cv1);
                v01 = make_float2(cc[0] * cv0 - cc[1] * sv0,
                                  cc[0] * sv0 + cc[1] * cv0);
                v23 = make_float2(cc[2] * cv1 - cc[3] * sv1,
                                  cc[2] * sv1 + cc[3] * cv1);
            }
            *(float2*)(Ot + (size_t)r0 * C_ + nn) = v01;
            *(float2*)(Ot + (size_t)r1 * C_ + nn) = v23;
        }
    }
}

// ===========================================================================
// MMA flash-attention, plain tf32 (exactly R10/R15 — 92us, passing).
// ===========================================================================
#define KP 68
#define VP 72
#define PP 36
#define OFF_K 0
#define OFF_V (OFF_K + 2*32*KP)
#define OFF_P (OFF_V + 2*32*VP)
#define ATTN_SMEM_BYTES ((OFF_P + 8*16*PP) * 4)   // 54272

__global__ __launch_bounds__(256, 2)
void attn_mma(const float* __restrict__ Q, const float* __restrict__ Kg,
              const float* __restrict__ Vg, float* __restrict__ Y)
{
    extern __shared__ float smf[];

    const int w = blockIdx.x >> 1, qseg = blockIdx.x & 1;
    const int h = blockIdx.y, b = blockIdx.z;
    const int tid  = threadIdx.x;
    const int wid  = tid >> 5, lane = tid & 31;
    const int g    = lane >> 2, tig = lane & 3;
    const size_t base = ((size_t)(b * T_ + w * W_)) * C_ + h * HD_;

    const int srow = tid >> 3;           // 0..31
    const int scol = (tid & 7) * 8;      // 0,8,..,56

    // ---- Q fragments (16 rows per warp), pre-scaled tf32 ----
    uint32_t qf[8][4];
    {
        const int qb = qseg * 128 + wid * 16;
        const float* Qp = Q + base + (size_t)qb * C_;
#pragma unroll
        for (int ks = 0; ks < 8; ks++) {
            const int cidx = ks * 8 + tig;
            qf[ks][0] = f2tf32(0.125f * Qp[(size_t)g * C_ + cidx]);
            qf[ks][1] = f2tf32(0.125f * Qp[(size_t)(g + 8) * C_ + cidx]);
            qf[ks][2] = f2tf32(0.125f * Qp[(size_t)g * C_ + cidx + 4]);
            qf[ks][3] = f2tf32(0.125f * Qp[(size_t)(g + 8) * C_ + cidx + 4]);
        }
    }

    // ---- stage chunk 0 into buf 0 ----
    {
        const float* kr = Kg + base + (size_t)srow * C_ + scol;
        const float* vr = Vg + base + (size_t)srow * C_ + scol;
#pragma unroll
        for (int hh = 0; hh < 2; hh++) {
            float4 kv = *(const float4*)(kr + hh * 4);
            *(uint4*)(smf + OFF_K + srow * KP + scol + hh * 4) =
                make_uint4(f2tf32(kv.x), f2tf32(kv.y), f2tf32(kv.z), f2tf32(kv.w));
            float4 vv = *(const float4*)(vr + hh * 4);
            *(uint4*)(smf + OFF_V + srow * VP + scol + hh * 4) =
                make_uint4(f2tf32(vv.x), f2tf32(vv.y), f2tf32(vv.z), f2tf32(vv.w));
        }
    }
    __syncthreads();

    float oacc[8][4];
#pragma unroll
    for (int nt = 0; nt < 8; nt++)
#pragma unroll
        for (int j = 0; j < 4; j++) oacc[nt][j] = 0.f;
    float mrow[2] = {-1e30f, -1e30f};
    float lrow[2] = {0.f, 0.f};

    float* Pw = smf + OFF_P + wid * 16 * PP;

    for (int c = 0; c < 8; c++) {
        const int buf = c & 1;

        // ---- stage next chunk into buf^1 ----
        if (c < 7) {
            const int kc1 = (c + 1) * 32;
            const float* kr = Kg + base + (size_t)(kc1 + srow) * C_ + scol;
            const float* vr = Vg + base + (size_t)(kc1 + srow) * C_ + scol;
            const int bofK = OFF_K + (buf ^ 1) * 32 * KP + srow * KP + scol;
            const int bofV = OFF_V + (buf ^ 1) * 32 * VP + srow * VP + scol;
#pragma unroll
            for (int hh = 0; hh < 2; hh++) {
                float4 kv = *(const float4*)(kr + hh * 4);
                *(uint4*)(smf + bofK + hh * 4) =
                    make_uint4(f2tf32(kv.x), f2tf32(kv.y), f2tf32(kv.z), f2tf32(kv.w));
                float4 vv = *(const float4*)(vr + hh * 4);
                *(uint4*)(smf + bofV + hh * 4) =
                    make_uint4(f2tf32(vv.x), f2tf32(vv.y), f2tf32(vv.z), f2tf32(vv.w));
            }
        }

        // ---- S = Q @ K^T ----
        const uint32_t* Ku = (const uint32_t*)(smf + OFF_K + buf * 32 * KP);
        float sacc[4][4];
#pragma unroll
        for (int nt = 0; nt < 4; nt++)
#pragma unroll
            for (int j = 0; j < 4; j++) sacc[nt][j] = 0.f;

#pragma unroll
        for (int ks = 0; ks < 8; ks++) {
#pragma unroll
            for (int nt = 0; nt < 4; nt++) {
                const int koff = (nt * 8 + g) * KP + ks * 8 + tig;
                uint32_t bk[2];
                bk[0] = Ku[koff];
                bk[1] = Ku[koff + 4];
                mma_tf32(sacc[nt], qf[ks], bk);
            }
        }

        // ---- online softmax; stage tf32-rounded P; l from rounded P ----
#pragma unroll
        for (int rr = 0; rr < 2; rr++) {
            float vmax = sacc[0][rr * 2];
#pragma unroll
            for (int nt = 0; nt < 4; nt++) {
                vmax = fmaxf(vmax, sacc[nt][rr * 2]);
                vmax = fmaxf(vmax, sacc[nt][rr * 2 + 1]);
            }
            vmax = fmaxf(vmax, __shfl_xor_sync(0xffffffffu, vmax, 1));
            vmax = fmaxf(vmax, __shfl_xor_sync(0xffffffffu, vmax, 2));
            const float mnew = fmaxf(mrow[rr], vmax);
            const float corr = __expf(mrow[rr] - mnew);
            float psum = 0.f;
            const int prow = (rr * 8 + g) * PP;
#pragma unroll
            for (int nt = 0; nt < 4; nt++) {
                uint32_t p0 = f2tf32(__expf(sacc[nt][rr * 2]     - mnew));
                uint32_t p1 = f2tf32(__expf(sacc[nt][rr * 2 + 1] - mnew));
                psum += __uint_as_float(p0) + __uint_as_float(p1);
                *(uint2*)(Pw + prow + nt * 8 + 2 * tig) = make_uint2(p0, p1);
            }
            psum += __shfl_xor_sync(0xffffffffu, psum, 1);
            psum += __shfl_xor_sync(0xffffffffu, psum, 2);
            lrow[rr] = lrow[rr] * corr + psum;
            mrow[rr] = mnew;
#pragma unroll
            for (int nt = 0; nt < 8; nt++) {
                oacc[nt][rr * 2]     *= corr;
                oacc[nt][rr * 2 + 1] *= corr;
            }
        }
        __syncwarp();

        // ---- O += P @ V ----
        const uint32_t* Vu = (const uint32_t*)(smf + OFF_V + buf * 32 * VP);
#pragma unroll
        for (int kt = 0; kt < 4; kt++) {
            uint32_t pa[4];
            const uint32_t* pp = (const uint32_t*)(Pw + g * PP + kt * 8 + tig);
            pa[0] = pp[0];
            pa[1] = pp[8 * PP];
            pa[2] = pp[4];
            pa[3] = pp[8 * PP + 4];
#pragma unroll
            for (int nt = 0; nt < 8; nt++) {
                const int voff = (kt * 8 + tig) * VP + nt * 8 + g;
                uint32_t bv[2];
                bv[0] = Vu[voff];
                bv[1] = Vu[voff + 4 * VP];
                mma_tf32(oacc[nt], pa, bv);
            }
        }
        __syncthreads();   // all reads of buf done; staged buf^1 visible
    }

    // ---- epilogue: normalize & store ----
    const float inv0 = 1.f / lrow[0], inv1 = 1.f / lrow[1];
    const int qb = qseg * 128 + wid * 16;
    float* Yp = Y + base + (size_t)qb * C_;
#pragma unroll
    for (int nt = 0; nt < 8; nt++) {
        const int d = nt * 8 + 2 * tig;
        *(float2*)(Yp + (size_t)g * C_ + d) =
            make_float2(oacc[nt][0] * inv0, oacc[nt][1] * inv0);
        *(float2*)(Yp + (size_t)(g + 8) * C_ + d) =
            make_float2(oacc[nt][2] * inv1, oacc[nt][3] * inv1);
    }
}

// ===========================================================================
extern "C" void kernel_launch(void* const* d_in, const int* in_sizes, int n_in,
                              void* d_out, int out_size)
{
    const float* x  = (const float*)d_in[0];
    const float* wq = (const float*)d_in[1];
    const float* wk = (const float*)d_in[2];
    const float* wv = (const float*)d_in[3];
    const float* wo = (const float*)d_in[4];
    float* out = (float*)d_out;

    float *q, *k, *v, *y;
    cudaGetSymbolAddress((void**)&q, g_q);
    cudaGetSymbolAddress((void**)&k, g_k);
    cudaGetSymbolAddress((void**)&v, g_v);
    cudaGetSymbolAddress((void**)&y, g_y);

    cudaFuncSetAttribute(gemm_fused, cudaFuncAttributeMaxDynamicSharedMemorySize, GEMM_SMEM_BYTES);
    cudaFuncSetAttribute(attn_mma, cudaFuncAttributeMaxDynamicSharedMemorySize, ATTN_SMEM_BYTES);

    // fused QKV: 12 slabs of 256 cols (4 per matrix); rope on q,k
    dim3 gqkv(12, M_ / 128);
    gemm_fused<<<gqkv, 512, GEMM_SMEM_BYTES>>>(x, wq, wk, wv, q, k, v, 0x3);

    dim3 ga(NW_ * 2, H_, B_);
    attn_mma<<<ga, 256, ATTN_SMEM_BYTES>>>(q, k, v, y);

    // output projection
    dim3 go(4, M_ / 128);
    gemm_fused<<<go, 512, GEMM_SMEM_BYTES>>>(y, wo, wo, wo, out, out, out, 0);
}

// round 17
// speedup vs baseline: 1.1638x; 1.1638x over previous
#include <cuda_runtime.h>
#include <cuda_fp16.h>
#include <math.h>
#include <stdint.h>

#define B_  2
#define T_  4096
#define C_  1024
#define H_  16
#define HD_ 64
#define W_  256
#define NW_ (T_/W_)
#define M_  (B_*T_)

// Scratch (no cudaMalloc allowed)
__device__ float g_q[(size_t)M_*C_];
__device__ float g_k[(size_t)M_*C_];
__device__ float g_v[(size_t)M_*C_];
__device__ float g_y[(size_t)M_*C_];

// ===========================================================================
// helpers (baseline ISA only)
// ===========================================================================
__device__ __forceinline__ uint32_t f2tf32(float f) {
    uint32_t r;
    asm("cvt.rna.tf32.f32 %0, %1;" : "=r"(r) : "f"(f));
    return r;
}

__device__ __forceinline__ uint32_t f2h2(float lo, float hi) {
    __half2 h = __floats2half2_rn(lo, hi);   // x = lo (low 16 bits)
    return *reinterpret_cast<uint32_t*>(&h);
}

// m16n8k8 tf32 MMA (attention kernel)
__device__ __forceinline__ void mma_tf32(float* d, const uint32_t* a, const uint32_t* b) {
    asm volatile(
        "mma.sync.aligned.m16n8k8.row.col.f32.tf32.tf32.f32 "
        "{%0,%1,%2,%3}, {%4,%5,%6,%7}, {%8,%9}, {%0,%1,%2,%3};"
        : "+f"(d[0]), "+f"(d[1]), "+f"(d[2]), "+f"(d[3])
        : "r"(a[0]), "r"(a[1]), "r"(a[2]), "r"(a[3]),
          "r"(b[0]), "r"(b[1]));
}

// m16n8k16 fp16 MMA, fp32 accumulate (GEMM kernel) — K=16 per instruction
__device__ __forceinline__ void mma_f16(float* d, const uint32_t* a, const uint32_t* b) {
    asm volatile(
        "mma.sync.aligned.m16n8k16.row.col.f32.f16.f16.f32 "
        "{%0,%1,%2,%3}, {%4,%5,%6,%7}, {%8,%9}, {%0,%1,%2,%3};"
        : "+f"(d[0]), "+f"(d[1]), "+f"(d[2]), "+f"(d[3])
        : "r"(a[0]), "r"(a[1]), "r"(a[2]), "r"(a[3]),
          "r"(b[0]), "r"(b[1]));
}

// ===========================================================================
// fp16 GEMM (NT): C[m][n] = sum_k A[m][k] * Wt[n][k], fp32 accumulate.
// Multi-weight fused: slab = blockIdx.x picks (mat, ncol0).
// CTA tile 128x256, 512 threads = 16 warps (2x8), warp tile 64x32
// (4 warps/SMSP). BK=32 -> 2 K=16 steps, 32 MMAs/warp/chunk (half of tf32).
// Tiles converted to fp16 AT STAGING (LDG float4 -> f16x2 pack -> STS.128),
// double-buffered smem (61KB). Row stride 40 halves = 20 words: fragment
// LDS bank pattern (g*20+tig) mod 32 is conflict-free for all 32 lanes.
// Accumulator layout identical to m16n8k8 -> rope epilogue unchanged.
// ===========================================================================
#define SAH 40                         // halves per tile row (stride)
#define SAW 20                         // words per tile row
#define A_H (128 * SAH)                // 5120 halves
#define B_H (256 * SAH)                // 10240 halves
#define STAGE_H (A_H + B_H)            // 15360 halves (30720 B)
#define GEMM_SMEM_BYTES (2 * STAGE_H * 2)   // 61440 B

__global__ __launch_bounds__(512)
void gemm_fused(const float* __restrict__ A,
                const float* __restrict__ W0, const float* __restrict__ W1,
                const float* __restrict__ W2,
                float* __restrict__ O0, float* __restrict__ O1,
                float* __restrict__ O2, int ropeMask)
{
    extern __shared__ __half smh[];
    uint32_t* smw = reinterpret_cast<uint32_t*>(smh);

    const int tid  = threadIdx.x;
    const int wid  = tid >> 5, lane = tid & 31;
    const int wm   = wid >> 3, wn = wid & 7;     // 2 x 8 warp grid
    const int g    = lane >> 2, tig = lane & 3;  // fragment coords
    const int slab = blockIdx.x;
    const int mat  = slab >> 2;
    const int ncol0 = (slab & 3) * 256;
    const int m0   = blockIdx.y * 128;

    const float* Wt = (mat == 0) ? W0 : ((mat == 1) ? W1 : W2);
    float*       Ot = (mat == 0) ? O0 : ((mat == 1) ? O1 : O2);
    const bool rope = (ropeMask >> mat) & 1;

    // staging mapping (512 threads, BK=32):
    // A tile 128x32: row = tid>>2, kb = (tid&3)*8  (8 halves = 1 STS.128)
    // B tile 256x32: row = tid>>1, kb = (tid&1)*16 (16 halves = 2 STS.128)
    const int arow = tid >> 2, akb = (tid & 3) * 8;
    const int brow = tid >> 1, bkb = (tid & 1) * 16;
    const float* AgK = A  + (size_t)(m0 + arow) * C_ + akb;
    const float* BgK = Wt + (size_t)(ncol0 + brow) * C_ + bkb;
    const int dA = arow * SAH + akb;           // half index
    const int dB = A_H + brow * SAH + bkb;

    float acc[16][4];
#pragma unroll
    for (int i = 0; i < 16; i++)
#pragma unroll
        for (int j = 0; j < 4; j++) acc[i][j] = 0.f;

    // register staging buffers (already converted to fp16 pairs)
    uint4 ra, rb0, rb1;

    auto ldcvt = [&](int k0) {
        float4 v0 = *(const float4*)(AgK + k0);
        float4 v1 = *(const float4*)(AgK + k0 + 4);
        ra  = make_uint4(f2h2(v0.x, v0.y), f2h2(v0.z, v0.w),
                         f2h2(v1.x, v1.y), f2h2(v1.z, v1.w));
        float4 w0 = *(const float4*)(BgK + k0);
        float4 w1 = *(const float4*)(BgK + k0 + 4);
        float4 w2 = *(const float4*)(BgK + k0 + 8);
        float4 w3 = *(const float4*)(BgK + k0 + 12);
        rb0 = make_uint4(f2h2(w0.x, w0.y), f2h2(w0.z, w0.w),
                         f2h2(w1.x, w1.y), f2h2(w1.z, w1.w));
        rb1 = make_uint4(f2h2(w2.x, w2.y), f2h2(w2.z, w2.w),
                         f2h2(w3.x, w3.y), f2h2(w3.z, w3.w));
    };
    auto sts = [&](int s) {
        const int off = s * STAGE_H;
        *(uint4*)(smh + off + dA)     = ra;
        *(uint4*)(smh + off + dB)     = rb0;
        *(uint4*)(smh + off + dB + 8) = rb1;
    };

    // ---- prologue: chunk 0 -> buf 0 ----
    ldcvt(0);
    sts(0);
    __syncthreads();

    for (int c = 0; c < 32; c++) {
        if (c < 31) ldcvt((c + 1) * 32);   // global prefetch (hidden by compute)

        const uint32_t* sAw = smw + (c & 1) * (STAGE_H / 2) + (wm * 64) * SAW;
        const uint32_t* sBw = smw + (c & 1) * (STAGE_H / 2) + (A_H / 2) + (wn * 32) * SAW;

#pragma unroll
        for (int ks = 0; ks < 2; ks++) {   // 2 x K=16
            const int kb = ks * 8;          // word offset
            uint32_t af[4][4], bf[4][2];
#pragma unroll
            for (int mt = 0; mt < 4; mt++) {
                const int base = (mt * 16 + g) * SAW + kb + tig;
                af[mt][0] = sAw[base];
                af[mt][1] = sAw[base + 8 * SAW];
                af[mt][2] = sAw[base + 4];
                af[mt][3] = sAw[base + 8 * SAW + 4];
            }
#pragma unroll
            for (int nt = 0; nt < 4; nt++) {
                const int base = (nt * 8 + g) * SAW + kb + tig;
                bf[nt][0] = sBw[base];
                bf[nt][1] = sBw[base + 4];
            }
#pragma unroll
            for (int mt = 0; mt < 4; mt++)
#pragma unroll
                for (int nt = 0; nt < 4; nt++)
                    mma_f16(acc[mt * 4 + nt], af[mt], bf[nt]);
        }

        if (c < 31) {
            __syncthreads();                // all reads of buf (c+1)&1 done (chunk c-1)
            sts((c + 1) & 1);
            __syncthreads();                // staged chunk c+1 visible
        }
    }

    // -------- epilogue (identical accumulator layout to m16n8k8) --------
    const int mbase = m0 + wm * 64;
    const int nbase = ncol0 + wn * 32;
#pragma unroll
    for (int nt = 0; nt < 4; nt++) {
        const int nn = nbase + nt * 8 + 2 * tig;
        float invf = 1.f, sv0, cv0, sv1, cv1;
        if (rope) {
            const int ip = (nn & (HD_ - 1)) >> 1;
            invf = (float)exp(-0.28782313662425572 * (double)ip); // ln(1e4)/32
        }
#pragma unroll
        for (int mt = 0; mt < 4; mt++) {
            const float* cc = acc[mt * 4 + nt];
            const int r0 = mbase + mt * 16 + g;
            const int r1 = r0 + 8;
            float2 v01 = make_float2(cc[0], cc[1]);
            float2 v23 = make_float2(cc[2], cc[3]);
            if (rope) {
                sincosf((float)(r0 & (T_ - 1)) * invf, &sv0, &cv0);
                sincosf((float)(r1 & (T_ - 1)) * invf, &sv1, &cv1);
                v01 = make_float2(cc[0] * cv0 - cc[1] * sv0,
                                  cc[0] * sv0 + cc[1] * cv0);
                v23 = make_float2(cc[2] * cv1 - cc[3] * sv1,
                                  cc[2] * sv1 + cc[3] * cv1);
            }
            *(float2*)(Ot + (size_t)r0 * C_ + nn) = v01;
            *(float2*)(Ot + (size_t)r1 * C_ + nn) = v23;
        }
    }
}

// ===========================================================================
// MMA flash-attention, plain tf32 (exactly R10/R15 — 92us, passing).
// ===========================================================================
#define KP 68
#define VP 72
#define PP 36
#define OFF_K 0
#define OFF_V (OFF_K + 2*32*KP)
#define OFF_P (OFF_V + 2*32*VP)
#define ATTN_SMEM_BYTES ((OFF_P + 8*16*PP) * 4)   // 54272

__global__ __launch_bounds__(256, 2)
void attn_mma(const float* __restrict__ Q, const float* __restrict__ Kg,
              const float* __restrict__ Vg, float* __restrict__ Y)
{
    extern __shared__ float smf[];

    const int w = blockIdx.x >> 1, qseg = blockIdx.x & 1;
    const int h = blockIdx.y, b = blockIdx.z;
    const int tid  = threadIdx.x;
    const int wid  = tid >> 5, lane = tid & 31;
    const int g    = lane >> 2, tig = lane & 3;
    const size_t base = ((size_t)(b * T_ + w * W_)) * C_ + h * HD_;

    const int srow = tid >> 3;           // 0..31
    const int scol = (tid & 7) * 8;      // 0,8,..,56

    // ---- Q fragments (16 rows per warp), pre-scaled tf32 ----
    uint32_t qf[8][4];
    {
        const int qb = qseg * 128 + wid * 16;
        const float* Qp = Q + base + (size_t)qb * C_;
#pragma unroll
        for (int ks = 0; ks < 8; ks++) {
            const int cidx = ks * 8 + tig;
            qf[ks][0] = f2tf32(0.125f * Qp[(size_t)g * C_ + cidx]);
            qf[ks][1] = f2tf32(0.125f * Qp[(size_t)(g + 8) * C_ + cidx]);
            qf[ks][2] = f2tf32(0.125f * Qp[(size_t)g * C_ + cidx + 4]);
            qf[ks][3] = f2tf32(0.125f * Qp[(size_t)(g + 8) * C_ + cidx + 4]);
        }
    }

    // ---- stage chunk 0 into buf 0 ----
    {
        const float* kr = Kg + base + (size_t)srow * C_ + scol;
        const float* vr = Vg + base + (size_t)srow * C_ + scol;
#pragma unroll
        for (int hh = 0; hh < 2; hh++) {
            float4 kv = *(const float4*)(kr + hh * 4);
            *(uint4*)(smf + OFF_K + srow * KP + scol + hh * 4) =
                make_uint4(f2tf32(kv.x), f2tf32(kv.y), f2tf32(kv.z), f2tf32(kv.w));
            float4 vv = *(const float4*)(vr + hh * 4);
            *(uint4*)(smf + OFF_V + srow * VP + scol + hh * 4) =
                make_uint4(f2tf32(vv.x), f2tf32(vv.y), f2tf32(vv.z), f2tf32(vv.w));
        }
    }
    __syncthreads();

    float oacc[8][4];
#pragma unroll
    for (int nt = 0; nt < 8; nt++)
#pragma unroll
        for (int j = 0; j < 4; j++) oacc[nt][j] = 0.f;
    float mrow[2] = {-1e30f, -1e30f};
    float lrow[2] = {0.f, 0.f};

    float* Pw = smf + OFF_P + wid * 16 * PP;

    for (int c = 0; c < 8; c++) {
        const int buf = c & 1;

        // ---- stage next chunk into buf^1 ----
        if (c < 7) {
            const int kc1 = (c + 1) * 32;
            const float* kr = Kg + base + (size_t)(kc1 + srow) * C_ + scol;
            const float* vr = Vg + base + (size_t)(kc1 + srow) * C_ + scol;
            const int bofK = OFF_K + (buf ^ 1) * 32 * KP + srow * KP + scol;
            const int bofV = OFF_V + (buf ^ 1) * 32 * VP + srow * VP + scol;
#pragma unroll
            for (int hh = 0; hh < 2; hh++) {
                float4 kv = *(const float4*)(kr + hh * 4);
                *(uint4*)(smf + bofK + hh * 4) =
                    make_uint4(f2tf32(kv.x), f2tf32(kv.y), f2tf32(kv.z), f2tf32(kv.w));
                float4 vv = *(const float4*)(vr + hh * 4);
                *(uint4*)(smf + bofV + hh * 4) =
                    make_uint4(f2tf32(vv.x), f2tf32(vv.y), f2tf32(vv.z), f2tf32(vv.w));
            }
        }

        // ---- S = Q @ K^T ----
        const uint32_t* Ku = (const uint32_t*)(smf + OFF_K + buf * 32 * KP);
        float sacc[4][4];
#pragma unroll
        for (int nt = 0; nt < 4; nt++)
#pragma unroll
            for (int j = 0; j < 4; j++) sacc[nt][j] = 0.f;

#pragma unroll
        for (int ks = 0; ks < 8; ks++) {
#pragma unroll
            for (int nt = 0; nt < 4; nt++) {
                const int koff = (nt * 8 + g) * KP + ks * 8 + tig;
                uint32_t bk[2];
                bk[0] = Ku[koff];
                bk[1] = Ku[koff + 4];
                mma_tf32(sacc[nt], qf[ks], bk);
            }
        }

        // ---- online softmax; stage tf32-rounded P; l from rounded P ----
#pragma unroll
        for (int rr = 0; rr < 2; rr++) {
            float vmax = sacc[0][rr * 2];
#pragma unroll
            for (int nt = 0; nt < 4; nt++) {
                vmax = fmaxf(vmax, sacc[nt][rr * 2]);
                vmax = fmaxf(vmax, sacc[nt][rr * 2 + 1]);
            }
            vmax = fmaxf(vmax, __shfl_xor_sync(0xffffffffu, vmax, 1));
            vmax = fmaxf(vmax, __shfl_xor_sync(0xffffffffu, vmax, 2));
            const float mnew = fmaxf(mrow[rr], vmax);
            const float corr = __expf(mrow[rr] - mnew);
            float psum = 0.f;
            const int prow = (rr * 8 + g) * PP;
#pragma unroll
            for (int nt = 0; nt < 4; nt++) {
                uint32_t p0 = f2tf32(__expf(sacc[nt][rr * 2]     - mnew));
                uint32_t p1 = f2tf32(__expf(sacc[nt][rr * 2 + 1] - mnew));
                psum += __uint_as_float(p0) + __uint_as_float(p1);
                *(uint2*)(Pw + prow + nt * 8 + 2 * tig) = make_uint2(p0, p1);
            }
            psum += __shfl_xor_sync(0xffffffffu, psum, 1);
            psum += __shfl_xor_sync(0xffffffffu, psum, 2);
            lrow[rr] = lrow[rr] * corr + psum;
            mrow[rr] = mnew;
#pragma unroll
            for (int nt = 0; nt < 8; nt++) {
                oacc[nt][rr * 2]     *= corr;
                oacc[nt][rr * 2 + 1] *= corr;
            }
        }
        __syncwarp();

        // ---- O += P @ V ----
        const uint32_t* Vu = (const uint32_t*)(smf + OFF_V + buf * 32 * VP);
#pragma unroll
        for (int kt = 0; kt < 4; kt++) {
            uint32_t pa[4];
            const uint32_t* pp = (const uint32_t*)(Pw + g * PP + kt * 8 + tig);
            pa[0] = pp[0];
            pa[1] = pp[8 * PP];
            pa[2] = pp[4];
            pa[3] = pp[8 * PP + 4];
#pragma unroll
            for (int nt = 0; nt < 8; nt++) {
                const int voff = (kt * 8 + tig) * VP + nt * 8 + g;
                uint32_t bv[2];
                bv[0] = Vu[voff];
                bv[1] = Vu[voff + 4 * VP];
                mma_tf32(oacc[nt], pa, bv);
            }
        }
        __syncthreads();   // all reads of buf done; staged buf^1 visible
    }

    // ---- epilogue: normalize & store ----
    const float inv0 = 1.f / lrow[0], inv1 = 1.f / lrow[1];
    const int qb = qseg * 128 + wid * 16;
    float* Yp = Y + base + (size_t)qb * C_;
#pragma unroll
    for (int nt = 0; nt < 8; nt++) {
        const int d = nt * 8 + 2 * tig;
        *(float2*)(Yp + (size_t)g * C_ + d) =
            make_float2(oacc[nt][0] * inv0, oacc[nt][1] * inv0);
        *(float2*)(Yp + (size_t)(g + 8) * C_ + d) =
            make_float2(oacc[nt][2] * inv1, oacc[nt][3] * inv1);
    }
}

// ===========================================================================
extern "C" void kernel_launch(void* const* d_in, const int* in_sizes, int n_in,
                              void* d_out, int out_size)
{
    const float* x  = (const float*)d_in[0];
    const float* wq = (const float*)d_in[1];
    const float* wk = (const float*)d_in[2];
    const float* wv = (const float*)d_in[3];
    const float* wo = (const float*)d_in[4];
    float* out = (float*)d_out;

    float *q, *k, *v, *y;
    cudaGetSymbolAddress((void**)&q, g_q);
    cudaGetSymbolAddress((void**)&k, g_k);
    cudaGetSymbolAddress((void**)&v, g_v);
    cudaGetSymbolAddress((void**)&y, g_y);

    cudaFuncSetAttribute(gemm_fused, cudaFuncAttributeMaxDynamicSharedMemorySize, GEMM_SMEM_BYTES);
    cudaFuncSetAttribute(attn_mma, cudaFuncAttributeMaxDynamicSharedMemorySize, ATTN_SMEM_BYTES);

    // fused QKV: 12 slabs of 256 cols (4 per matrix); rope on q,k
    dim3 gqkv(12, M_ / 128);
    gemm_fused<<<gqkv, 512, GEMM_SMEM_BYTES>>>(x, wq, wk, wv, q, k, v, 0x3);

    dim3 ga(NW_ * 2, H_, B_);
    attn_mma<<<ga, 256, ATTN_SMEM_BYTES>>>(q, k, v, y);

    // output projection
    dim3 go(4, M_ / 128);
    gemm_fused<<<go, 512, GEMM_SMEM_BYTES>>>(y, wo, wo, wo, out, out, out, 0);
}